// round 5
// baseline (speedup 1.0000x reference)
#include <cuda_runtime.h>
#include <cuda_bf16.h>
#include <cstdint>

// Embedding gather: out[b,s,:] = embedding[input_ids[b,s],:]
// input_ids: [2,2048] int32 -> 4096 tokens
// embedding: [32000,1024] fp32
// out:       [4096,1024] fp32
//
// R5 = R3/R4 resubmit (broker timeouts; kernel still untested).
// 8 rows per CTA, 8 independent float4 gathers in flight per thread (MLP=8)
// to hide DRAM latency. Index phase uses 2x int4 loads.

#define FEATURES 1024
#define VEC4 (FEATURES / 4)   // 256 float4 per row
#define ROWS_PER_CTA 8

__global__ __launch_bounds__(256)
void wordembed_gather_kernel(const int* __restrict__ input_ids,
                             const float4* __restrict__ embedding,
                             float4* __restrict__ out,
                             int n_tokens) {
    int base = blockIdx.x * ROWS_PER_CTA;
    int t = threadIdx.x;   // 0..255 = one float4 column of each row

    // Phase 1: load 8 indices as two int4 (uniform across CTA, L1 broadcast)
    const int4* idp = (const int4*)(input_ids + base);
    int4 i0 = __ldg(&idp[0]);
    int4 i1 = __ldg(&idp[1]);
    int idx[ROWS_PER_CTA] = {i0.x, i0.y, i0.z, i0.w, i1.x, i1.y, i1.z, i1.w};

    // Phase 2: 8 independent 16B gathers (front-batched -> MLP=8)
    float4 v[ROWS_PER_CTA];
    #pragma unroll
    for (int r = 0; r < ROWS_PER_CTA; r++) {
        v[r] = __ldg(&embedding[(size_t)idx[r] * VEC4 + t]);
    }

    // Phase 3: 8 coalesced 16B stores
    #pragma unroll
    for (int r = 0; r < ROWS_PER_CTA; r++) {
        out[(size_t)(base + r) * VEC4 + t] = v[r];
    }
}

extern "C" void kernel_launch(void* const* d_in, const int* in_sizes, int n_in,
                              void* d_out, int out_size) {
    const int*    input_ids = (const int*)d_in[0];
    const float4* embedding = (const float4*)d_in[1];
    float4*       out       = (float4*)d_out;

    int n_tokens = in_sizes[0];    // 4096
    int n_ctas = n_tokens / ROWS_PER_CTA;   // 512

    wordembed_gather_kernel<<<n_ctas, 256>>>(input_ids, embedding, out, n_tokens);
}

// round 7
// speedup vs baseline: 1.0332x; 1.0332x over previous
#include <cuda_runtime.h>
#include <cuda_bf16.h>
#include <cstdint>

// Embedding gather via TMA bulk-copy engine (sm_103a).
// out[row,:] = embedding[ids[row],:], 4096 rows x 4KB.
//
// R7 = R6 resubmit (broker timeout; untested). Bypass LSU: each CTA
// (32 threads, lane 0 drives) handles 8 rows: 8x cp.async.bulk 4KB loads
// GMEM->SMEM all in flight (mbarrier completion), then cp.async.bulk
// stores SMEM->GMEM as they land. 512 CTAs x 32KB = 16MB in flight.

#define ROW_BYTES 4096
#define ROWS_PER_CTA 8

__device__ __forceinline__ uint32_t smem_u32(const void* p) {
    uint32_t a;
    asm("{ .reg .u64 t; cvta.to.shared.u64 t, %1; cvt.u32.u64 %0, t; }"
        : "=r"(a) : "l"(p));
    return a;
}

__global__ __launch_bounds__(32)
void wordembed_tma_kernel(const int* __restrict__ input_ids,
                          const char* __restrict__ embedding,
                          char* __restrict__ out) {
    __shared__ alignas(128) char buf[ROWS_PER_CTA][ROW_BYTES];
    __shared__ alignas(8) unsigned long long mbar[ROWS_PER_CTA];

    const int tid  = threadIdx.x;
    const int base = blockIdx.x * ROWS_PER_CTA;

    if (tid == 0) {
        #pragma unroll
        for (int i = 0; i < ROWS_PER_CTA; i++) {
            uint32_t mb = smem_u32(&mbar[i]);
            asm volatile("mbarrier.init.shared.b64 [%0], %1;"
                         :: "r"(mb), "r"(1) : "memory");
        }
    }
    __syncthreads();

    if (tid == 0) {
        // Indices: two int4 loads (32B aligned: base % 8 == 0)
        const int4* idp = (const int4*)(input_ids + base);
        int4 a = __ldg(&idp[0]);
        int4 b = __ldg(&idp[1]);
        int idx[ROWS_PER_CTA] = {a.x, a.y, a.z, a.w, b.x, b.y, b.z, b.w};

        // Issue all 8 bulk loads (fully in flight)
        #pragma unroll
        for (int i = 0; i < ROWS_PER_CTA; i++) {
            uint32_t mb = smem_u32(&mbar[i]);
            uint32_t sa = smem_u32(&buf[i][0]);
            const char* src = embedding + (size_t)idx[i] * ROW_BYTES;
            asm volatile("mbarrier.arrive.expect_tx.shared.b64 _, [%0], %1;"
                         :: "r"(mb), "r"((uint32_t)ROW_BYTES) : "memory");
            asm volatile(
                "cp.async.bulk.shared::cluster.global.mbarrier::complete_tx::bytes "
                "[%0], [%1], %2, [%3];"
                :: "r"(sa), "l"(src), "r"((uint32_t)ROW_BYTES), "r"(mb)
                : "memory");
        }

        // Drain in order: wait load i, then bulk-store it out
        #pragma unroll
        for (int i = 0; i < ROWS_PER_CTA; i++) {
            uint32_t mb = smem_u32(&mbar[i]);
            // try_wait loop, parity 0
            asm volatile(
                "{\n\t"
                ".reg .pred P;\n\t"
                "WL_%=:\n\t"
                "mbarrier.try_wait.parity.shared.b64 P, [%0], 0, 0x989680;\n\t"
                "@P bra.uni WD_%=;\n\t"
                "bra.uni WL_%=;\n\t"
                "WD_%=:\n\t"
                "}"
                :: "r"(mb) : "memory");

            uint32_t sa = smem_u32(&buf[i][0]);
            char* dst = out + (size_t)(base + i) * ROW_BYTES;
            asm volatile(
                "cp.async.bulk.global.shared::cta.bulk_group [%0], [%1], %2;"
                :: "l"(dst), "r"(sa), "r"((uint32_t)ROW_BYTES)
                : "memory");
        }
        asm volatile("cp.async.bulk.commit_group;" ::: "memory");
        asm volatile("cp.async.bulk.wait_group 0;" ::: "memory");
    }
    __syncthreads();
}

extern "C" void kernel_launch(void* const* d_in, const int* in_sizes, int n_in,
                              void* d_out, int out_size) {
    const int*  input_ids = (const int*)d_in[0];
    const char* embedding = (const char*)d_in[1];
    char*       out       = (char*)d_out;

    int n_tokens = in_sizes[0];                 // 4096
    int n_ctas = n_tokens / ROWS_PER_CTA;       // 512

    wordembed_tma_kernel<<<n_ctas, 32>>>(input_ids, embedding, out);
}